// round 7
// baseline (speedup 1.0000x reference)
#include <cuda_runtime.h>

// FraudDetectionHybrid — autoencoder branch is dead code (recon unused).
// R5: single graph node (no constant-memory memcpys — they cost ~1.3us/node of
// replay overhead in R4). Weights via 12 broadcast __ldg vector loads.
// 8 samples/thread, block=128, grid=1024 -> 8 blocks/SM, single wave.
// Both sigmoids via tanh.approx: sigmoid(x) = 0.5 + 0.5*tanh(x/2)
// -> 10 MUFU/sample total, no __expf/__fdividef chains.

__device__ __forceinline__ float tanh_fast(float x) {
    float y;
    asm("tanh.approx.f32 %0, %1;" : "=f"(y) : "f"(x));
    return y;
}

__global__ __launch_bounds__(128, 8)
void fraud_kernel(const float4* __restrict__ x4,
                  const float4* __restrict__ fraud_W,   // [4,2,2] = 4 float4
                  const float4* __restrict__ fraud_b,   // [4,2]   = 2 float4
                  const float4* __restrict__ conv_k,    // [2,2]   = 1 float4
                  const float4* __restrict__ s_W1,      // [4,2]   = 2 float4
                  const float4* __restrict__ s_b1,      // [4]     = 1 float4
                  const float4* __restrict__ s_W2,      // [2,4]   = 2 float4
                  const float2* __restrict__ s_b2,      // [2]     = 1 float2
                  float4* __restrict__ out4)
{
    const int base = blockIdx.x * 512 + threadIdx.x;   // 512 float4 per block

    // ---- broadcast weight loads (uniform addresses, L1-resident) ----
    const float4 w0  = __ldg(fraud_W + 0);
    const float4 w1  = __ldg(fraud_W + 1);
    const float4 w2  = __ldg(fraud_W + 2);
    const float4 w3  = __ldg(fraud_W + 3);
    const float4 fb0 = __ldg(fraud_b + 0);   // layers 0,1 biases
    const float4 fb1 = __ldg(fraud_b + 1);   // layers 2,3 biases
    const float4 ck  = __ldg(conv_k);
    const float4 W1a = __ldg(s_W1 + 0);      // sampler rows 0,1
    const float4 W1b = __ldg(s_W1 + 1);      // sampler rows 2,3
    const float4 b1  = __ldg(s_b1);
    const float4 W2a = __ldg(s_W2 + 0);
    const float4 W2b = __ldg(s_W2 + 1);
    const float2 b2  = __ldg(s_b2);

    const float c0  = ck.x + ck.z;
    const float c1  = ck.y + ck.w;
    const float dW0 = W2b.x - W2a.x;
    const float dW1 = W2b.y - W2a.y;
    const float dW2 = W2b.z - W2a.z;
    const float dW3 = W2b.w - W2a.w;
    const float db  = b2.y - b2.x;

    // process one sample (x0,x1) -> (p0,p1)
    auto process = [&](float h0, float h1, float& p0, float& p1) {
        // fraud net: 4 stacked 2x2 affine + tanh
        {
            float z0 = fmaf(w0.x, h0, fmaf(w0.y, h1, fb0.x));
            float z1 = fmaf(w0.z, h0, fmaf(w0.w, h1, fb0.y));
            h0 = tanh_fast(z0); h1 = tanh_fast(z1);
            z0 = fmaf(w1.x, h0, fmaf(w1.y, h1, fb0.z));
            z1 = fmaf(w1.z, h0, fmaf(w1.w, h1, fb0.w));
            h0 = tanh_fast(z0); h1 = tanh_fast(z1);
            z0 = fmaf(w2.x, h0, fmaf(w2.y, h1, fb1.x));
            z1 = fmaf(w2.z, h0, fmaf(w2.w, h1, fb1.y));
            h0 = tanh_fast(z0); h1 = tanh_fast(z1);
            z0 = fmaf(w3.x, h0, fmaf(w3.y, h1, fb1.z));
            z1 = fmaf(w3.z, h0, fmaf(w3.w, h1, fb1.w));
            h0 = tanh_fast(z0); h1 = tanh_fast(z1);
        }
        // collapsed 2x2 conv + sigmoid (tanh form)
        float zc   = fmaf(c0, h0, c1 * h1);
        float conv = fmaf(tanh_fast(0.5f * zc), 0.5f, 0.5f);
        // sampler: 2 -> 4 (tanh)
        float t0 = tanh_fast(fmaf(W1a.x, h0, fmaf(W1a.y, conv, b1.x)));
        float t1 = tanh_fast(fmaf(W1a.z, h0, fmaf(W1a.w, conv, b1.y)));
        float t2 = tanh_fast(fmaf(W1b.x, h0, fmaf(W1b.y, conv, b1.z)));
        float t3 = tanh_fast(fmaf(W1b.z, h0, fmaf(W1b.w, conv, b1.w)));
        // softmax over 2 logits: p1 = sigmoid(l1-l0), p0 = 1 - p1
        float dl = fmaf(t3, dW3, fmaf(t2, dW2, fmaf(t1, dW1, fmaf(t0, dW0, db))));
        float s  = tanh_fast(0.5f * dl);
        p1 = fmaf(s,  0.5f, 0.5f);
        p0 = fmaf(s, -0.5f, 0.5f);
    };

#pragma unroll
    for (int k = 0; k < 4; k++) {
        float4 in = x4[base + k * 128];          // coalesced
        float pa0, pa1, pb0, pb1;
        process(in.x, in.y, pa0, pa1);
        process(in.z, in.w, pb0, pb1);
        out4[base + k * 128] = make_float4(pa0, pa1, pb0, pb1);
    }
}

extern "C" void kernel_launch(void* const* d_in, const int* in_sizes, int n_in,
                              void* d_out, int out_size)
{
    const int n4 = in_sizes[0] / 4;        // total float4 in x (B/2)
    const int block = 128;
    const int grid = n4 / 512;             // 512 float4 per block; B=1<<20 -> 1024

    fraud_kernel<<<grid, block>>>(
        (const float4*)d_in[0],            // x
        (const float4*)d_in[1],            // fraud_W
        (const float4*)d_in[2],            // fraud_b
        (const float4*)d_in[15],           // conv_k
        (const float4*)d_in[16],           // s_W1
        (const float4*)d_in[17],           // s_b1
        (const float4*)d_in[18],           // s_W2
        (const float2*)d_in[19],           // s_b2
        (float4*)d_out);
}

// round 8
// speedup vs baseline: 1.0332x; 1.0332x over previous
#include <cuda_runtime.h>

// FraudDetectionHybrid — autoencoder branch is dead code (recon unused).
// R8: latency was the binder (occ 33%, issue 33%, all pipes <13% in R7).
// Trade per-thread ILP for warp parallelism: 2 samples/thread, block=256,
// grid=2048 -> 16384 warps (4x R7), ~48 regs -> ~40 resident warps/SM.
// Goal: saturate the MUFU pipe (floor ~2.5us for 10 tanh.approx/sample).

__device__ __forceinline__ float tanh_fast(float x) {
    float y;
    asm("tanh.approx.f32 %0, %1;" : "=f"(y) : "f"(x));
    return y;
}

__global__ __launch_bounds__(256, 5)
void fraud_kernel(const float4* __restrict__ x4,
                  const float4* __restrict__ fraud_W,   // [4,2,2] = 4 float4
                  const float4* __restrict__ fraud_b,   // [4,2]   = 2 float4
                  const float4* __restrict__ conv_k,    // [2,2]   = 1 float4
                  const float4* __restrict__ s_W1,      // [4,2]   = 2 float4
                  const float4* __restrict__ s_b1,      // [4]     = 1 float4
                  const float4* __restrict__ s_W2,      // [2,4]   = 2 float4
                  const float2* __restrict__ s_b2,      // [2]     = 1 float2
                  float4* __restrict__ out4,
                  int n4)
{
    const int t = blockIdx.x * blockDim.x + threadIdx.x;
    if (t >= n4) return;

    // input load first: get the long-latency DRAM access in flight before
    // the (L1-resident broadcast) weight loads and derived-constant math.
    const float4 in = x4[t];

    // ---- broadcast weight loads (uniform addresses, L1-hit after warmup) ----
    const float4 w0  = __ldg(fraud_W + 0);
    const float4 w1  = __ldg(fraud_W + 1);
    const float4 w2  = __ldg(fraud_W + 2);
    const float4 w3  = __ldg(fraud_W + 3);
    const float4 fb0 = __ldg(fraud_b + 0);   // layers 0,1 biases
    const float4 fb1 = __ldg(fraud_b + 1);   // layers 2,3 biases
    const float4 ck  = __ldg(conv_k);
    const float4 W1a = __ldg(s_W1 + 0);      // sampler rows 0,1
    const float4 W1b = __ldg(s_W1 + 1);      // sampler rows 2,3
    const float4 b1  = __ldg(s_b1);
    const float4 W2a = __ldg(s_W2 + 0);
    const float4 W2b = __ldg(s_W2 + 1);
    const float2 b2  = __ldg(s_b2);

    // fold conv kernel and output layer into derived constants
    const float c0  = ck.x + ck.z;
    const float c1  = ck.y + ck.w;
    const float dW0 = W2b.x - W2a.x;
    const float dW1 = W2b.y - W2a.y;
    const float dW2 = W2b.z - W2a.z;
    const float dW3 = W2b.w - W2a.w;
    const float db  = b2.y - b2.x;

    auto process = [&](float h0, float h1, float& p0, float& p1) {
        // fraud net: 4 stacked 2x2 affine + tanh
        float z0 = fmaf(w0.x, h0, fmaf(w0.y, h1, fb0.x));
        float z1 = fmaf(w0.z, h0, fmaf(w0.w, h1, fb0.y));
        h0 = tanh_fast(z0); h1 = tanh_fast(z1);
        z0 = fmaf(w1.x, h0, fmaf(w1.y, h1, fb0.z));
        z1 = fmaf(w1.z, h0, fmaf(w1.w, h1, fb0.w));
        h0 = tanh_fast(z0); h1 = tanh_fast(z1);
        z0 = fmaf(w2.x, h0, fmaf(w2.y, h1, fb1.x));
        z1 = fmaf(w2.z, h0, fmaf(w2.w, h1, fb1.y));
        h0 = tanh_fast(z0); h1 = tanh_fast(z1);
        z0 = fmaf(w3.x, h0, fmaf(w3.y, h1, fb1.z));
        z1 = fmaf(w3.z, h0, fmaf(w3.w, h1, fb1.w));
        h0 = tanh_fast(z0); h1 = tanh_fast(z1);
        // collapsed 2x2 conv + sigmoid via tanh
        float zc   = fmaf(c0, h0, c1 * h1);
        float conv = fmaf(tanh_fast(0.5f * zc), 0.5f, 0.5f);
        // sampler: 2 -> 4 (tanh)
        float t0 = tanh_fast(fmaf(W1a.x, h0, fmaf(W1a.y, conv, b1.x)));
        float t1 = tanh_fast(fmaf(W1a.z, h0, fmaf(W1a.w, conv, b1.y)));
        float t2 = tanh_fast(fmaf(W1b.x, h0, fmaf(W1b.y, conv, b1.z)));
        float t3 = tanh_fast(fmaf(W1b.z, h0, fmaf(W1b.w, conv, b1.w)));
        // 2-way softmax == sigmoid of logit difference
        float dl = fmaf(t3, dW3, fmaf(t2, dW2, fmaf(t1, dW1, fmaf(t0, dW0, db))));
        float s  = tanh_fast(0.5f * dl);
        p1 = fmaf(s,  0.5f, 0.5f);
        p0 = fmaf(s, -0.5f, 0.5f);
    };

    float pa0, pa1, pb0, pb1;
    process(in.x, in.y, pa0, pa1);
    process(in.z, in.w, pb0, pb1);
    out4[t] = make_float4(pa0, pa1, pb0, pb1);
}

extern "C" void kernel_launch(void* const* d_in, const int* in_sizes, int n_in,
                              void* d_out, int out_size)
{
    const int n4 = in_sizes[0] / 4;        // float4 count (2 samples each); B=1<<20 -> 524288
    const int block = 256;
    const int grid = (n4 + block - 1) / block;   // 2048 blocks

    fraud_kernel<<<grid, block>>>(
        (const float4*)d_in[0],            // x
        (const float4*)d_in[1],            // fraud_W
        (const float4*)d_in[2],            // fraud_b
        (const float4*)d_in[15],           // conv_k
        (const float4*)d_in[16],           // s_W1
        (const float4*)d_in[17],           // s_b1
        (const float4*)d_in[18],           // s_W2
        (const float2*)d_in[19],           // s_b2
        (float4*)d_out,
        n4);
}